// round 1
// baseline (speedup 1.0000x reference)
#include <cuda_runtime.h>

#define N_NODES 100000
#define E_EDGES 3200000
#define D_DIM   16
#define H_DIM   128
#define TILE_M  64
#define NT      ((N_NODES + TILE_M - 1) / TILE_M)
#define LN_EPS  1e-5f

// ---------------- scratch (static device arrays; no allocation) --------------
__device__ __align__(16) float g_agg_in [N_NODES * D_DIM];
__device__ __align__(16) float g_agg_out[N_NODES * D_DIM];

// ---------------- zero init --------------------------------------------------
__global__ void zero_kernel() {
    int i = blockIdx.x * blockDim.x + threadIdx.x;
    const int total = N_NODES * D_DIM / 4;
    if (i < total) {
        ((float4*)g_agg_in )[i] = make_float4(0.f, 0.f, 0.f, 0.f);
        ((float4*)g_agg_out)[i] = make_float4(0.f, 0.f, 0.f, 0.f);
    }
}

// ---------------- edge scatter ----------------------------------------------
__device__ __forceinline__ void red_add_v4(float* p, float a, float b, float c, float d) {
    asm volatile("red.global.add.v4.f32 [%0], {%1,%2,%3,%4};"
                 :: "l"(p), "f"(a), "f"(b), "f"(c), "f"(d) : "memory");
}

__global__ void __launch_bounds__(256)
scatter_kernel(const float* __restrict__ nodes,
               const int2*  __restrict__ edges,
               const float* __restrict__ ew) {
    int tid = blockIdx.x * 256 + threadIdx.x;
    int e = tid >> 2;
    if (e >= E_EDGES) return;
    int c4 = (tid & 3) * 4;
    int2  sd = edges[e];
    float w  = ew[e];
    float4 ns = *(const float4*)&nodes[sd.x * D_DIM + c4];
    float4 nd = *(const float4*)&nodes[sd.y * D_DIM + c4];
    // agg_in[dst] += nodes[src]*w ; agg_out[src] += nodes[dst]*w
    red_add_v4(&g_agg_in [sd.y * D_DIM + c4], ns.x * w, ns.y * w, ns.z * w, ns.w * w);
    red_add_v4(&g_agg_out[sd.x * D_DIM + c4], nd.x * w, nd.y * w, nd.z * w, nd.w * w);
}

// ---------------- fused MLP -------------------------------------------------
// smem layout (floats):
//  W1s[48*128]=6144 @0 | W2s[128*128]=16384 @6144 | W3s @22528 | W4s[128*16]=2048 @38912
//  Pb[1200] @40960 | Xs[64*48]=3072 @42160 | Hs[64*132]=8448 @45232  -> total 53680 f
#define OFF_W1 0
#define OFF_W2 6144
#define OFF_W3 22528
#define OFF_W4 38912
#define OFF_PB 40960
#define OFF_X  42160
#define OFF_H  45232
#define SMEM_FLOATS 53680
#define SMEM_BYTES  (SMEM_FLOATS * 4)
#define LDH 132

template <int K, int LDA>
__device__ __forceinline__ void gemm_tile(const float* __restrict__ A,
                                          const float* __restrict__ B,
                                          int m0, int n0, float c[8][4]) {
#pragma unroll
    for (int i = 0; i < 8; i++)
#pragma unroll
        for (int j = 0; j < 4; j++) c[i][j] = 0.f;

#pragma unroll 2
    for (int k = 0; k < K; k += 2) {
        float2 a[8];
#pragma unroll
        for (int i = 0; i < 8; i++)
            a[i] = *(const float2*)&A[(m0 + i) * LDA + k];
        float4 b0 = *(const float4*)&B[k * H_DIM + n0];
        float4 b1 = *(const float4*)&B[(k + 1) * H_DIM + n0];
#pragma unroll
        for (int i = 0; i < 8; i++) {
            c[i][0] = fmaf(a[i].x, b0.x, c[i][0]);
            c[i][1] = fmaf(a[i].x, b0.y, c[i][1]);
            c[i][2] = fmaf(a[i].x, b0.z, c[i][2]);
            c[i][3] = fmaf(a[i].x, b0.w, c[i][3]);
            c[i][0] = fmaf(a[i].y, b1.x, c[i][0]);
            c[i][1] = fmaf(a[i].y, b1.y, c[i][1]);
            c[i][2] = fmaf(a[i].y, b1.z, c[i][2]);
            c[i][3] = fmaf(a[i].y, b1.w, c[i][3]);
        }
    }
}

// bias add -> store Hs -> LayerNorm(128) + tanh in place
__device__ __forceinline__ void epilogue_ln(float c[8][4], float* __restrict__ Hs,
                                            const float* __restrict__ bias,
                                            const float* __restrict__ gain,
                                            const float* __restrict__ beta,
                                            int m0, int n0, int tid) {
    __syncthreads();  // all reads of Hs (as GEMM A) done before overwrite
#pragma unroll
    for (int i = 0; i < 8; i++) {
        float4 v;
        v.x = c[i][0] + bias[n0 + 0];
        v.y = c[i][1] + bias[n0 + 1];
        v.z = c[i][2] + bias[n0 + 2];
        v.w = c[i][3] + bias[n0 + 3];
        *(float4*)&Hs[(m0 + i) * LDH + n0] = v;
    }
    __syncthreads();
    // LN: 4 lanes per row (32 elems each)
    int r = tid >> 2, seg = tid & 3;
    float* row = &Hs[r * LDH + seg * 32];
    float h[32];
    float s = 0.f, s2 = 0.f;
#pragma unroll
    for (int u = 0; u < 32; u++) { h[u] = row[u]; s += h[u]; s2 += h[u] * h[u]; }
    s  += __shfl_xor_sync(0xffffffffu, s, 1);
    s2 += __shfl_xor_sync(0xffffffffu, s2, 1);
    s  += __shfl_xor_sync(0xffffffffu, s, 2);
    s2 += __shfl_xor_sync(0xffffffffu, s2, 2);
    float m   = s * (1.0f / 128.0f);
    float var = fmaxf(s2 * (1.0f / 128.0f) - m * m, 0.0f);
    float rs  = rsqrtf(var + LN_EPS);
#pragma unroll
    for (int u = 0; u < 32; u++) {
        int col = seg * 32 + u;
        row[u] = tanhf((h[u] - m) * rs * gain[col] + beta[col]);
    }
    __syncthreads();
}

__global__ void __launch_bounds__(256, 1)
mlp_kernel(const float* __restrict__ nodes,
           const float* __restrict__ W1, const float* __restrict__ b1,
           const float* __restrict__ g1, const float* __restrict__ be1,
           const float* __restrict__ W2, const float* __restrict__ b2,
           const float* __restrict__ g2, const float* __restrict__ be2,
           const float* __restrict__ W3, const float* __restrict__ b3,
           const float* __restrict__ g3, const float* __restrict__ be3,
           const float* __restrict__ W4, const float* __restrict__ b4,
           const float* __restrict__ g4, const float* __restrict__ be4,
           float* __restrict__ out) {
    extern __shared__ float sm[];
    float* W1s = sm + OFF_W1;
    float* W2s = sm + OFF_W2;
    float* W3s = sm + OFF_W3;
    float* W4s = sm + OFF_W4;
    float* Pb  = sm + OFF_PB;
    float* Xs  = sm + OFF_X;
    float* Hs  = sm + OFF_H;
    const int tid = threadIdx.x;

    // stage all weights once per block (persistent kernel)
    {
        for (int i = tid; i < 6144;  i += 256) W1s[i] = W1[i];
        for (int i = tid; i < 16384; i += 256) W2s[i] = W2[i];
        for (int i = tid; i < 16384; i += 256) W3s[i] = W3[i];
        for (int i = tid; i < 2048;  i += 256) W4s[i] = W4[i];
        for (int i = tid; i < 128; i += 256) {
            Pb[0    + i] = b1[i]; Pb[128  + i] = g1[i]; Pb[256  + i] = be1[i];
            Pb[384  + i] = b2[i]; Pb[512  + i] = g2[i]; Pb[640  + i] = be2[i];
            Pb[768  + i] = b3[i]; Pb[896  + i] = g3[i]; Pb[1024 + i] = be3[i];
        }
        for (int i = tid; i < 16; i += 256) {
            Pb[1152 + i] = b4[i]; Pb[1168 + i] = g4[i]; Pb[1184 + i] = be4[i];
        }
    }
    __syncthreads();

    const int tx = tid & 31, ty = tid >> 5;
    const int n0 = tx * 4, m0 = ty * 8;

    for (int t = blockIdx.x; t < NT; t += gridDim.x) {
        const int nbase = t * TILE_M;

        // ---- load X tile: [64][48] = concat(agg_in, agg_out, nodes) ----
        for (int idx = tid; idx < TILE_M * 12; idx += 256) {
            int r = idx / 12, q = idx % 12;
            int node = nbase + r;
            float4 v = make_float4(0.f, 0.f, 0.f, 0.f);
            if (node < N_NODES) {
                int part = q >> 2, sub = (q & 3) * 4;
                const float* src = (part == 0) ? &g_agg_in[node * D_DIM]
                                 : (part == 1) ? &g_agg_out[node * D_DIM]
                                               : &nodes[node * D_DIM];
                v = *(const float4*)&src[sub];
            }
            *(float4*)&Xs[r * 48 + q * 4] = v;
        }
        __syncthreads();

        float c[8][4];
        // layer 1: [64,48]@[48,128]
        gemm_tile<48, 48>(Xs, W1s, m0, n0, c);
        epilogue_ln(c, Hs, Pb + 0, Pb + 128, Pb + 256, m0, n0, tid);
        // layer 2: [64,128]@[128,128]
        gemm_tile<128, LDH>(Hs, W2s, m0, n0, c);
        epilogue_ln(c, Hs, Pb + 384, Pb + 512, Pb + 640, m0, n0, tid);
        // layer 3
        gemm_tile<128, LDH>(Hs, W3s, m0, n0, c);
        epilogue_ln(c, Hs, Pb + 768, Pb + 896, Pb + 1024, m0, n0, tid);

        // ---- layer 4: [64,128]@[128,16], LN(16)+tanh, write out ----
        {
            const int txw = tid & 15, tyw = tid >> 4;
            float c4[4] = {0.f, 0.f, 0.f, 0.f};
            for (int k = 0; k < 128; k += 2) {
                float b0 = W4s[k * 16 + txw];
                float bv = W4s[(k + 1) * 16 + txw];
#pragma unroll
                for (int i = 0; i < 4; i++) {
                    float2 a = *(const float2*)&Hs[(tyw * 4 + i) * LDH + k];
                    c4[i] = fmaf(a.x, b0, c4[i]);
                    c4[i] = fmaf(a.y, bv, c4[i]);
                }
            }
#pragma unroll
            for (int i = 0; i < 4; i++) {
                float y = c4[i] + Pb[1152 + txw];
                float s = y, s2 = y * y;
#pragma unroll
                for (int o = 1; o < 16; o <<= 1) {
                    s  += __shfl_xor_sync(0xffffffffu, s, o);
                    s2 += __shfl_xor_sync(0xffffffffu, s2, o);
                }
                float mm  = s * (1.0f / 16.0f);
                float var = fmaxf(s2 * (1.0f / 16.0f) - mm * mm, 0.0f);
                float rs  = rsqrtf(var + LN_EPS);
                float o4  = tanhf((y - mm) * rs * Pb[1168 + txw] + Pb[1184 + txw]);
                int node = nbase + tyw * 4 + i;
                if (node < N_NODES) out[node * D_DIM + txw] = o4;
            }
        }
        __syncthreads();
    }
}

// ---------------- launch -----------------------------------------------------
extern "C" void kernel_launch(void* const* d_in, const int* in_sizes, int n_in,
                              void* d_out, int out_size) {
    const float* nodes = (const float*)d_in[0];
    const int2*  edges = (const int2*) d_in[1];
    const float* ew    = (const float*)d_in[2];
    const float* W1 = (const float*)d_in[3];
    const float* b1 = (const float*)d_in[4];
    const float* g1 = (const float*)d_in[5];
    const float* be1= (const float*)d_in[6];
    const float* W2 = (const float*)d_in[7];
    const float* b2 = (const float*)d_in[8];
    const float* g2 = (const float*)d_in[9];
    const float* be2= (const float*)d_in[10];
    const float* W3 = (const float*)d_in[11];
    const float* b3 = (const float*)d_in[12];
    const float* g3 = (const float*)d_in[13];
    const float* be3= (const float*)d_in[14];
    const float* W4 = (const float*)d_in[15];
    const float* b4 = (const float*)d_in[16];
    const float* g4 = (const float*)d_in[17];
    const float* be4= (const float*)d_in[18];
    float* out = (float*)d_out;

    // zero agg buffers
    zero_kernel<<<(N_NODES * D_DIM / 4 + 255) / 256, 256>>>();
    // edge scatter (4 threads per edge)
    scatter_kernel<<<(E_EDGES * 4 + 255) / 256, 256>>>(nodes, edges, ew);
    // fused MLP, persistent grid = #SMs (1 block/SM due to 214KB smem)
    int smCount = 148;
    cudaDeviceGetAttribute(&smCount, cudaDevAttrMultiProcessorCount, 0);
    cudaFuncSetAttribute(mlp_kernel, cudaFuncAttributeMaxDynamicSharedMemorySize, SMEM_BYTES);
    mlp_kernel<<<smCount, 256, SMEM_BYTES>>>(nodes,
                                             W1, b1, g1, be1,
                                             W2, b2, g2, be2,
                                             W3, b3, g3, be3,
                                             W4, b4, g4, be4,
                                             out);
}

// round 3
// speedup vs baseline: 1.8663x; 1.8663x over previous
#include <cuda_runtime.h>
#include <cuda_bf16.h>
#include <cstdint>

#define N_NODES 100000
#define E_EDGES 3200000
#define NTILES  6250        // 100000 / 16 exactly
#define LN_EPS  1e-5f

// ---------------- scratch ----------------------------------------------------
__device__ __align__(16) float g_agg_in [N_NODES * 16];
__device__ __align__(16) float g_agg_out[N_NODES * 16];

// ---------------- zero init --------------------------------------------------
__global__ void zero_kernel() {
    int i = blockIdx.x * blockDim.x + threadIdx.x;
    const int total = N_NODES * 16 / 4;
    if (i < total) {
        ((float4*)g_agg_in )[i] = make_float4(0.f, 0.f, 0.f, 0.f);
        ((float4*)g_agg_out)[i] = make_float4(0.f, 0.f, 0.f, 0.f);
    }
}

// ---------------- edge scatter ----------------------------------------------
__device__ __forceinline__ void red_add_v4(float* p, float a, float b, float c, float d) {
    asm volatile("red.global.add.v4.f32 [%0], {%1,%2,%3,%4};"
                 :: "l"(p), "f"(a), "f"(b), "f"(c), "f"(d) : "memory");
}

__global__ void __launch_bounds__(256)
scatter_kernel(const float* __restrict__ nodes,
               const int2*  __restrict__ edges,
               const float* __restrict__ ew) {
    int tid = blockIdx.x * 256 + threadIdx.x;
    int e = tid >> 2;
    if (e >= E_EDGES) return;
    int c4 = (tid & 3) * 4;
    int2  sd = edges[e];
    float w  = ew[e];
    float4 ns = *(const float4*)&nodes[sd.x * 16 + c4];
    float4 nd = *(const float4*)&nodes[sd.y * 16 + c4];
    red_add_v4(&g_agg_in [sd.y * 16 + c4], ns.x * w, ns.y * w, ns.z * w, ns.w * w);
    red_add_v4(&g_agg_out[sd.x * 16 + c4], nd.x * w, nd.y * w, nd.z * w, nd.w * w);
}

// ================= warp-MMA MLP (mma.sync bf16, 3-term split) ================
// SMEM (u32 units): weights k-pair-packed bf16x2, per-n-row stride pads chosen
// so stride % 8 == 4 -> conflict-free fragment loads.
//  L1: 128 rows x 52  (hi kk[0,24), lo kk[24,48))   @0      6656
//  L2: 128 rows x 132 (hi [0,64), lo [64,128))      @6656   16896
//  L3: 128 rows x 132                               @23552  16896
//  L4: 16  rows x 132                               @40448  2112
//  Pb: 1200 floats                                  @42560
#define OFF_L1 0
#define OFF_L2 6656
#define OFF_L3 23552
#define OFF_L4 40448
#define OFF_PB 42560
#define SMEM_U32 (OFF_PB + 1200)
#define SMEM_BYTES (SMEM_U32 * 4)
#define S1 52
#define S2 132

__device__ __forceinline__ void mma16816(float d[4], const uint32_t a[4],
                                         uint32_t b0, uint32_t b1) {
    asm volatile("mma.sync.aligned.m16n8k16.row.col.f32.bf16.bf16.f32 "
                 "{%0,%1,%2,%3}, {%4,%5,%6,%7}, {%8,%9}, {%0,%1,%2,%3};"
                 : "+f"(d[0]), "+f"(d[1]), "+f"(d[2]), "+f"(d[3])
                 : "r"(a[0]), "r"(a[1]), "r"(a[2]), "r"(a[3]), "r"(b0), "r"(b1));
}

__device__ __forceinline__ uint32_t pack_hi(float a, float b, float& ra, float& rb) {
    __nv_bfloat162 h2 = __floats2bfloat162_rn(a, b);
    ra = a - __bfloat162float(h2.x);
    rb = b - __bfloat162float(h2.y);
    return *reinterpret_cast<uint32_t*>(&h2);
}
__device__ __forceinline__ uint32_t pack_bf(float a, float b) {
    __nv_bfloat162 h2 = __floats2bfloat162_rn(a, b);
    return *reinterpret_cast<uint32_t*>(&h2);
}

// stage W[K][N] -> dst[n*stride + kk] : hi kk in [0,K/2), lo kk in [K/2,K)
__device__ void stage_w(const float* __restrict__ W, uint32_t* __restrict__ dst,
                        int K, int N, int stride, int tid) {
    const int half = K >> 1;
    for (int idx = tid; idx < N * half; idx += 256) {
        int n = idx / half, kk = idx - n * half;
        float w0 = W[(2 * kk) * N + n];
        float w1 = W[(2 * kk + 1) * N + n];
        float r0, r1;
        uint32_t hi = pack_hi(w0, w1, r0, r1);
        dst[n * stride + kk]        = hi;
        dst[n * stride + half + kk] = pack_bf(r0, r1);
    }
}

// D[nt][4] += 3-term A x Wsm   (KT = K/16 tiles, NTt = N/8 tiles)
template <int KT, int NTt>
__device__ __forceinline__ void layer_mma(const uint32_t Ahi[][4], const uint32_t Alo[][4],
                                          const uint32_t* __restrict__ Wsm, const int stride,
                                          int grp, int tig, float D[][4]) {
#pragma unroll
    for (int nt = 0; nt < NTt; nt++) {
        const uint32_t* row = Wsm + (nt * 8 + grp) * stride;
        D[nt][0] = 0.f; D[nt][1] = 0.f; D[nt][2] = 0.f; D[nt][3] = 0.f;
#pragma unroll
        for (int kt = 0; kt < KT; kt++) {
            uint32_t bh0 = row[kt * 8 + tig];
            uint32_t bh1 = row[kt * 8 + 4 + tig];
            uint32_t bl0 = row[KT * 8 + kt * 8 + tig];
            uint32_t bl1 = row[KT * 8 + kt * 8 + 4 + tig];
            mma16816(D[nt], Ahi[kt], bh0, bh1);   // xhi * whi
            mma16816(D[nt], Alo[kt], bh0, bh1);   // xlo * whi
            mma16816(D[nt], Ahi[kt], bl0, bl1);   // xhi * wlo
        }
    }
}

// bias + LN(128) + tanh on D, emit next-layer A fragments (hi/lo)
__device__ __forceinline__ void epi128(float D[][4], const float* __restrict__ Pb, int base,
                                       int tig, uint32_t Ahi[][4], uint32_t Alo[][4]) {
    const float* bias = Pb + base;
    const float* gain = Pb + base + 128;
    const float* beta = Pb + base + 256;
    float s0 = 0.f, q0 = 0.f, s1 = 0.f, q1 = 0.f;
#pragma unroll
    for (int nt = 0; nt < 16; nt++) {
        float2 bb = *(const float2*)&bias[nt * 8 + tig * 2];
        D[nt][0] += bb.x; D[nt][1] += bb.y;
        D[nt][2] += bb.x; D[nt][3] += bb.y;
        s0 += D[nt][0] + D[nt][1];
        q0 = fmaf(D[nt][0], D[nt][0], fmaf(D[nt][1], D[nt][1], q0));
        s1 += D[nt][2] + D[nt][3];
        q1 = fmaf(D[nt][2], D[nt][2], fmaf(D[nt][3], D[nt][3], q1));
    }
    s0 += __shfl_xor_sync(0xffffffffu, s0, 1); q0 += __shfl_xor_sync(0xffffffffu, q0, 1);
    s0 += __shfl_xor_sync(0xffffffffu, s0, 2); q0 += __shfl_xor_sync(0xffffffffu, q0, 2);
    s1 += __shfl_xor_sync(0xffffffffu, s1, 1); q1 += __shfl_xor_sync(0xffffffffu, q1, 1);
    s1 += __shfl_xor_sync(0xffffffffu, s1, 2); q1 += __shfl_xor_sync(0xffffffffu, q1, 2);
    float m0 = s0 * (1.0f / 128.0f);
    float v0 = fmaxf(q0 * (1.0f / 128.0f) - m0 * m0, 0.0f);
    float rs0 = rsqrtf(v0 + LN_EPS);
    float m1 = s1 * (1.0f / 128.0f);
    float v1 = fmaxf(q1 * (1.0f / 128.0f) - m1 * m1, 0.0f);
    float rs1 = rsqrtf(v1 + LN_EPS);
#pragma unroll
    for (int kt = 0; kt < 8; kt++) {
#pragma unroll
        for (int h = 0; h < 2; h++) {
            int nt = 2 * kt + h;
            float2 gg = *(const float2*)&gain[nt * 8 + tig * 2];
            float2 be = *(const float2*)&beta[nt * 8 + tig * 2];
            float y0 = tanhf(fmaf((D[nt][0] - m0) * rs0, gg.x, be.x));
            float y1 = tanhf(fmaf((D[nt][1] - m0) * rs0, gg.y, be.y));
            float y2 = tanhf(fmaf((D[nt][2] - m1) * rs1, gg.x, be.x));
            float y3 = tanhf(fmaf((D[nt][3] - m1) * rs1, gg.y, be.y));
            float ra, rb;
            Ahi[kt][0 + 2 * h] = pack_hi(y0, y1, ra, rb);
            Alo[kt][0 + 2 * h] = pack_bf(ra, rb);
            Ahi[kt][1 + 2 * h] = pack_hi(y2, y3, ra, rb);
            Alo[kt][1 + 2 * h] = pack_bf(ra, rb);
        }
    }
}

__global__ void __launch_bounds__(256, 1)
mlp_kernel(const float* __restrict__ nodes,
           const float* __restrict__ W1, const float* __restrict__ b1,
           const float* __restrict__ g1, const float* __restrict__ be1,
           const float* __restrict__ W2, const float* __restrict__ b2,
           const float* __restrict__ g2, const float* __restrict__ be2,
           const float* __restrict__ W3, const float* __restrict__ b3,
           const float* __restrict__ g3, const float* __restrict__ be3,
           const float* __restrict__ W4, const float* __restrict__ b4,
           const float* __restrict__ g4, const float* __restrict__ be4,
           float* __restrict__ out) {
    extern __shared__ uint32_t smw[];
    float* Pb = (float*)(smw + OFF_PB);
    const int tid = threadIdx.x;

    // ---- stage weights ----
    stage_w(W1, smw + OFF_L1,  48, 128, S1, tid);
    stage_w(W2, smw + OFF_L2, 128, 128, S2, tid);
    stage_w(W3, smw + OFF_L3, 128, 128, S2, tid);
    stage_w(W4, smw + OFF_L4, 128,  16, S2, tid);
    for (int i = tid; i < 128; i += 256) {
        Pb[0 + i]   = b1[i]; Pb[128 + i] = g1[i]; Pb[256 + i]  = be1[i];
        Pb[384 + i] = b2[i]; Pb[512 + i] = g2[i]; Pb[640 + i]  = be2[i];
        Pb[768 + i] = b3[i]; Pb[896 + i] = g3[i]; Pb[1024 + i] = be3[i];
    }
    for (int i = tid; i < 16; i += 256) {
        Pb[1152 + i] = b4[i]; Pb[1168 + i] = g4[i]; Pb[1184 + i] = be4[i];
    }
    __syncthreads();

    const int warp = tid >> 5, lane = tid & 31;
    const int grp = lane >> 2, tig = lane & 3;

    uint32_t Ahi[8][4], Alo[8][4];
    float D[16][4];

    for (int t = blockIdx.x * 8 + warp; t < NTILES; t += gridDim.x * 8) {
        const int r0 = t * 16 + grp, r1 = r0 + 8;

        // ---- layer-1 A fragments from [agg_in | agg_out | nodes] ----
#pragma unroll
        for (int kt = 0; kt < 3; kt++) {
            const float* S = (kt == 0) ? g_agg_in : (kt == 1) ? g_agg_out : nodes;
            float2 x00 = *(const float2*)&S[r0 * 16 + tig * 2];
            float2 x01 = *(const float2*)&S[r0 * 16 + 8 + tig * 2];
            float2 x10 = *(const float2*)&S[r1 * 16 + tig * 2];
            float2 x11 = *(const float2*)&S[r1 * 16 + 8 + tig * 2];
            float ra, rb;
            Ahi[kt][0] = pack_hi(x00.x, x00.y, ra, rb); Alo[kt][0] = pack_bf(ra, rb);
            Ahi[kt][1] = pack_hi(x10.x, x10.y, ra, rb); Alo[kt][1] = pack_bf(ra, rb);
            Ahi[kt][2] = pack_hi(x01.x, x01.y, ra, rb); Alo[kt][2] = pack_bf(ra, rb);
            Ahi[kt][3] = pack_hi(x11.x, x11.y, ra, rb); Alo[kt][3] = pack_bf(ra, rb);
        }

        layer_mma<3, 16>(Ahi, Alo, smw + OFF_L1, S1, grp, tig, D);
        epi128(D, Pb, 0, tig, Ahi, Alo);
        layer_mma<8, 16>(Ahi, Alo, smw + OFF_L2, S2, grp, tig, D);
        epi128(D, Pb, 384, tig, Ahi, Alo);
        layer_mma<8, 16>(Ahi, Alo, smw + OFF_L3, S2, grp, tig, D);
        epi128(D, Pb, 768, tig, Ahi, Alo);
        layer_mma<8, 2>(Ahi, Alo, smw + OFF_L4, S2, grp, tig, D);

        // ---- layer-4 epilogue: LN(16)+tanh, write out ----
        {
            float2 bb0 = *(const float2*)&Pb[1152 + tig * 2];
            float2 bb1 = *(const float2*)&Pb[1152 + 8 + tig * 2];
            float v00 = D[0][0] + bb0.x, v01 = D[0][1] + bb0.y;
            float v02 = D[1][0] + bb1.x, v03 = D[1][1] + bb1.y;
            float v10 = D[0][2] + bb0.x, v11 = D[0][3] + bb0.y;
            float v12 = D[1][2] + bb1.x, v13 = D[1][3] + bb1.y;
            float s0 = (v00 + v01) + (v02 + v03);
            float q0 = fmaf(v00, v00, fmaf(v01, v01, fmaf(v02, v02, v03 * v03)));
            float s1 = (v10 + v11) + (v12 + v13);
            float q1 = fmaf(v10, v10, fmaf(v11, v11, fmaf(v12, v12, v13 * v13)));
            s0 += __shfl_xor_sync(0xffffffffu, s0, 1); q0 += __shfl_xor_sync(0xffffffffu, q0, 1);
            s0 += __shfl_xor_sync(0xffffffffu, s0, 2); q0 += __shfl_xor_sync(0xffffffffu, q0, 2);
            s1 += __shfl_xor_sync(0xffffffffu, s1, 1); q1 += __shfl_xor_sync(0xffffffffu, q1, 1);
            s1 += __shfl_xor_sync(0xffffffffu, s1, 2); q1 += __shfl_xor_sync(0xffffffffu, q1, 2);
            float m0 = s0 * (1.0f / 16.0f);
            float w0 = fmaxf(q0 * (1.0f / 16.0f) - m0 * m0, 0.0f);
            float rs0 = rsqrtf(w0 + LN_EPS);
            float m1 = s1 * (1.0f / 16.0f);
            float w1 = fmaxf(q1 * (1.0f / 16.0f) - m1 * m1, 0.0f);
            float rs1 = rsqrtf(w1 + LN_EPS);
            float2 gg0 = *(const float2*)&Pb[1168 + tig * 2];
            float2 gg1 = *(const float2*)&Pb[1168 + 8 + tig * 2];
            float2 be0 = *(const float2*)&Pb[1184 + tig * 2];
            float2 be1v = *(const float2*)&Pb[1184 + 8 + tig * 2];
            float2 o;
            o.x = tanhf(fmaf((v00 - m0) * rs0, gg0.x, be0.x));
            o.y = tanhf(fmaf((v01 - m0) * rs0, gg0.y, be0.y));
            *(float2*)&out[r0 * 16 + tig * 2] = o;
            o.x = tanhf(fmaf((v02 - m0) * rs0, gg1.x, be1v.x));
            o.y = tanhf(fmaf((v03 - m0) * rs0, gg1.y, be1v.y));
            *(float2*)&out[r0 * 16 + 8 + tig * 2] = o;
            o.x = tanhf(fmaf((v10 - m1) * rs1, gg0.x, be0.x));
            o.y = tanhf(fmaf((v11 - m1) * rs1, gg0.y, be0.y));
            *(float2*)&out[r1 * 16 + tig * 2] = o;
            o.x = tanhf(fmaf((v12 - m1) * rs1, gg1.x, be1v.x));
            o.y = tanhf(fmaf((v13 - m1) * rs1, gg1.y, be1v.y));
            *(float2*)&out[r1 * 16 + 8 + tig * 2] = o;
        }
    }
}

// ---------------- launch -----------------------------------------------------
extern "C" void kernel_launch(void* const* d_in, const int* in_sizes, int n_in,
                              void* d_out, int out_size) {
    const float* nodes = (const float*)d_in[0];
    const int2*  edges = (const int2*) d_in[1];
    const float* ew    = (const float*)d_in[2];
    const float* W1 = (const float*)d_in[3];
    const float* b1 = (const float*)d_in[4];
    const float* g1 = (const float*)d_in[5];
    const float* be1= (const float*)d_in[6];
    const float* W2 = (const float*)d_in[7];
    const float* b2 = (const float*)d_in[8];
    const float* g2 = (const float*)d_in[9];
    const float* be2= (const float*)d_in[10];
    const float* W3 = (const float*)d_in[11];
    const float* b3 = (const float*)d_in[12];
    const float* g3 = (const float*)d_in[13];
    const float* be3= (const float*)d_in[14];
    const float* W4 = (const float*)d_in[15];
    const float* b4 = (const float*)d_in[16];
    const float* g4 = (const float*)d_in[17];
    const float* be4= (const float*)d_in[18];
    float* out = (float*)d_out;

    zero_kernel<<<(N_NODES * 16 / 4 + 255) / 256, 256>>>();
    scatter_kernel<<<(E_EDGES * 4 + 255) / 256, 256>>>(nodes, edges, ew);

    int smCount = 148;
    cudaDeviceGetAttribute(&smCount, cudaDevAttrMultiProcessorCount, 0);
    cudaFuncSetAttribute(mlp_kernel, cudaFuncAttributeMaxDynamicSharedMemorySize, SMEM_BYTES);
    mlp_kernel<<<smCount, 256, SMEM_BYTES>>>(nodes,
                                             W1, b1, g1, be1,
                                             W2, b2, g2, be2,
                                             W3, b3, g3, be3,
                                             W4, b4, g4, be4,
                                             out);
}

// round 4
// speedup vs baseline: 1.8729x; 1.0035x over previous
#include <cuda_runtime.h>
#include <cuda_bf16.h>
#include <cstdint>

#define N_NODES 100000
#define E_EDGES 3200000
#define NTILES  6250        // 100000 / 16 exactly
#define LN_EPS  1e-5f

// ---------------- scratch ----------------------------------------------------
__device__ __align__(16) float g_agg_in [N_NODES * 16];
__device__ __align__(16) float g_agg_out[N_NODES * 16];

// ---------------- edge scatter ----------------------------------------------
__device__ __forceinline__ void red_add_v4(float* p, float a, float b, float c, float d) {
    asm volatile("red.global.add.v4.f32 [%0], {%1,%2,%3,%4};"
                 :: "l"(p), "f"(a), "f"(b), "f"(c), "f"(d) : "memory");
}

__global__ void __launch_bounds__(256)
scatter_kernel(const float* __restrict__ nodes,
               const int2*  __restrict__ edges,
               const float* __restrict__ ew) {
    int tid = blockIdx.x * 256 + threadIdx.x;
    int e = tid >> 2;
    if (e >= E_EDGES) return;
    int c4 = (tid & 3) * 4;
    int2  sd = edges[e];
    float w  = ew[e];
    float4 ns = *(const float4*)&nodes[sd.x * 16 + c4];
    float4 nd = *(const float4*)&nodes[sd.y * 16 + c4];
    red_add_v4(&g_agg_in [sd.y * 16 + c4], ns.x * w, ns.y * w, ns.z * w, ns.w * w);
    red_add_v4(&g_agg_out[sd.x * 16 + c4], nd.x * w, nd.y * w, nd.z * w, nd.w * w);
}

// ================= warp-MMA MLP (mma.sync bf16, 3-term split) ================
// SMEM (u32 units): weights k-pair-packed bf16x2, per-n-row stride pads chosen
// so stride % 8 == 4 -> conflict-free fragment loads.
#define OFF_L1 0
#define OFF_L2 6656
#define OFF_L3 23552
#define OFF_L4 40448
#define OFF_PB 42560
#define SMEM_U32 (OFF_PB + 1200)
#define SMEM_BYTES (SMEM_U32 * 4)
#define S1 52
#define S2 132

__device__ __forceinline__ void mma16816(float d[4], const uint32_t a[4],
                                         uint32_t b0, uint32_t b1) {
    asm volatile("mma.sync.aligned.m16n8k16.row.col.f32.bf16.bf16.f32 "
                 "{%0,%1,%2,%3}, {%4,%5,%6,%7}, {%8,%9}, {%0,%1,%2,%3};"
                 : "+f"(d[0]), "+f"(d[1]), "+f"(d[2]), "+f"(d[3])
                 : "r"(a[0]), "r"(a[1]), "r"(a[2]), "r"(a[3]), "r"(b0), "r"(b1));
}

__device__ __forceinline__ uint32_t pack_hi(float a, float b, float& ra, float& rb) {
    __nv_bfloat162 h2 = __floats2bfloat162_rn(a, b);
    ra = a - __bfloat162float(h2.x);
    rb = b - __bfloat162float(h2.y);
    return *reinterpret_cast<uint32_t*>(&h2);
}
__device__ __forceinline__ uint32_t pack_bf(float a, float b) {
    __nv_bfloat162 h2 = __floats2bfloat162_rn(a, b);
    return *reinterpret_cast<uint32_t*>(&h2);
}

// fast tanh: MUFU.EX2-based, ~1e-6 rel error (inputs LN-bounded)
__device__ __forceinline__ float ftanh(float x) {
    float t = fminf(fmaxf(2.0f * x, -60.0f), 60.0f);
    float e = __expf(t);
    return __fdividef(e - 1.0f, e + 1.0f);
}

// stage W[K][N] -> dst[n*stride + kk] : hi kk in [0,K/2), lo kk in [K/2,K)
__device__ void stage_w(const float* __restrict__ W, uint32_t* __restrict__ dst,
                        int K, int N, int stride, int tid) {
    const int half = K >> 1;
    for (int idx = tid; idx < N * half; idx += 256) {
        int n = idx / half, kk = idx - n * half;
        float w0 = W[(2 * kk) * N + n];
        float w1 = W[(2 * kk + 1) * N + n];
        float r0, r1;
        uint32_t hi = pack_hi(w0, w1, r0, r1);
        dst[n * stride + kk]        = hi;
        dst[n * stride + half + kk] = pack_bf(r0, r1);
    }
}

// D[nt][4] += 3-term A x Wsm   (KT = K/16 tiles, NTt = N/8 tiles)
template <int KT, int NTt>
__device__ __forceinline__ void layer_mma(const uint32_t Ahi[][4], const uint32_t Alo[][4],
                                          const uint32_t* __restrict__ Wsm, const int stride,
                                          int grp, int tig, float D[][4]) {
#pragma unroll
    for (int nt = 0; nt < NTt; nt++) {
        const uint32_t* row = Wsm + (nt * 8 + grp) * stride;
        D[nt][0] = 0.f; D[nt][1] = 0.f; D[nt][2] = 0.f; D[nt][3] = 0.f;
#pragma unroll
        for (int kt = 0; kt < KT; kt++) {
            uint32_t bh0 = row[kt * 8 + tig];
            uint32_t bh1 = row[kt * 8 + 4 + tig];
            uint32_t bl0 = row[KT * 8 + kt * 8 + tig];
            uint32_t bl1 = row[KT * 8 + kt * 8 + 4 + tig];
            mma16816(D[nt], Ahi[kt], bh0, bh1);   // xhi * whi
            mma16816(D[nt], Alo[kt], bh0, bh1);   // xlo * whi
            mma16816(D[nt], Ahi[kt], bl0, bl1);   // xhi * wlo
        }
    }
}

// bias + LN(128) + tanh on D, emit next-layer A fragments (hi/lo)
__device__ __forceinline__ void epi128(float D[][4], const float* __restrict__ Pb, int base,
                                       int tig, uint32_t Ahi[][4], uint32_t Alo[][4]) {
    const float* bias = Pb + base;
    const float* gain = Pb + base + 128;
    const float* beta = Pb + base + 256;
    float s0 = 0.f, q0 = 0.f, s1 = 0.f, q1 = 0.f;
#pragma unroll
    for (int nt = 0; nt < 16; nt++) {
        float2 bb = *(const float2*)&bias[nt * 8 + tig * 2];
        D[nt][0] += bb.x; D[nt][1] += bb.y;
        D[nt][2] += bb.x; D[nt][3] += bb.y;
        s0 += D[nt][0] + D[nt][1];
        q0 = fmaf(D[nt][0], D[nt][0], fmaf(D[nt][1], D[nt][1], q0));
        s1 += D[nt][2] + D[nt][3];
        q1 = fmaf(D[nt][2], D[nt][2], fmaf(D[nt][3], D[nt][3], q1));
    }
    s0 += __shfl_xor_sync(0xffffffffu, s0, 1); q0 += __shfl_xor_sync(0xffffffffu, q0, 1);
    s0 += __shfl_xor_sync(0xffffffffu, s0, 2); q0 += __shfl_xor_sync(0xffffffffu, q0, 2);
    s1 += __shfl_xor_sync(0xffffffffu, s1, 1); q1 += __shfl_xor_sync(0xffffffffu, q1, 1);
    s1 += __shfl_xor_sync(0xffffffffu, s1, 2); q1 += __shfl_xor_sync(0xffffffffu, q1, 2);
    float m0 = s0 * (1.0f / 128.0f);
    float v0 = fmaxf(q0 * (1.0f / 128.0f) - m0 * m0, 0.0f);
    float rs0 = rsqrtf(v0 + LN_EPS);
    float m1 = s1 * (1.0f / 128.0f);
    float v1 = fmaxf(q1 * (1.0f / 128.0f) - m1 * m1, 0.0f);
    float rs1 = rsqrtf(v1 + LN_EPS);
#pragma unroll
    for (int kt = 0; kt < 8; kt++) {
#pragma unroll
        for (int h = 0; h < 2; h++) {
            int nt = 2 * kt + h;
            float2 gg = *(const float2*)&gain[nt * 8 + tig * 2];
            float2 be = *(const float2*)&beta[nt * 8 + tig * 2];
            float y0 = ftanh(fmaf((D[nt][0] - m0) * rs0, gg.x, be.x));
            float y1 = ftanh(fmaf((D[nt][1] - m0) * rs0, gg.y, be.y));
            float y2 = ftanh(fmaf((D[nt][2] - m1) * rs1, gg.x, be.x));
            float y3 = ftanh(fmaf((D[nt][3] - m1) * rs1, gg.y, be.y));
            float ra, rb;
            Ahi[kt][0 + 2 * h] = pack_hi(y0, y1, ra, rb);
            Alo[kt][0 + 2 * h] = pack_bf(ra, rb);
            Ahi[kt][1 + 2 * h] = pack_hi(y2, y3, ra, rb);
            Alo[kt][1 + 2 * h] = pack_bf(ra, rb);
        }
    }
}

__global__ void __launch_bounds__(256, 1)
mlp_kernel(const float* __restrict__ nodes,
           const float* __restrict__ W1, const float* __restrict__ b1,
           const float* __restrict__ g1, const float* __restrict__ be1,
           const float* __restrict__ W2, const float* __restrict__ b2,
           const float* __restrict__ g2, const float* __restrict__ be2,
           const float* __restrict__ W3, const float* __restrict__ b3,
           const float* __restrict__ g3, const float* __restrict__ be3,
           const float* __restrict__ W4, const float* __restrict__ b4,
           const float* __restrict__ g4, const float* __restrict__ be4,
           float* __restrict__ out) {
    extern __shared__ uint32_t smw[];
    float* Pb = (float*)(smw + OFF_PB);
    const int tid = threadIdx.x;

    // ---- stage weights ----
    stage_w(W1, smw + OFF_L1,  48, 128, S1, tid);
    stage_w(W2, smw + OFF_L2, 128, 128, S2, tid);
    stage_w(W3, smw + OFF_L3, 128, 128, S2, tid);
    stage_w(W4, smw + OFF_L4, 128,  16, S2, tid);
    for (int i = tid; i < 128; i += 256) {
        Pb[0 + i]   = b1[i]; Pb[128 + i] = g1[i]; Pb[256 + i]  = be1[i];
        Pb[384 + i] = b2[i]; Pb[512 + i] = g2[i]; Pb[640 + i]  = be2[i];
        Pb[768 + i] = b3[i]; Pb[896 + i] = g3[i]; Pb[1024 + i] = be3[i];
    }
    for (int i = tid; i < 16; i += 256) {
        Pb[1152 + i] = b4[i]; Pb[1168 + i] = g4[i]; Pb[1184 + i] = be4[i];
    }
    __syncthreads();

    const int warp = tid >> 5, lane = tid & 31;
    const int grp = lane >> 2, tig = lane & 3;

    uint32_t Ahi[8][4], Alo[8][4];
    float D[16][4];

    for (int t = blockIdx.x * 8 + warp; t < NTILES; t += gridDim.x * 8) {
        const int r0 = t * 16 + grp, r1 = r0 + 8;

        // ---- layer-1 A fragments from [agg_in | agg_out | nodes] ----
#pragma unroll
        for (int kt = 0; kt < 3; kt++) {
            const float* S = (kt == 0) ? g_agg_in : (kt == 1) ? g_agg_out : nodes;
            float2 x00 = *(const float2*)&S[r0 * 16 + tig * 2];
            float2 x01 = *(const float2*)&S[r0 * 16 + 8 + tig * 2];
            float2 x10 = *(const float2*)&S[r1 * 16 + tig * 2];
            float2 x11 = *(const float2*)&S[r1 * 16 + 8 + tig * 2];
            float ra, rb;
            Ahi[kt][0] = pack_hi(x00.x, x00.y, ra, rb); Alo[kt][0] = pack_bf(ra, rb);
            Ahi[kt][1] = pack_hi(x10.x, x10.y, ra, rb); Alo[kt][1] = pack_bf(ra, rb);
            Ahi[kt][2] = pack_hi(x01.x, x01.y, ra, rb); Alo[kt][2] = pack_bf(ra, rb);
            Ahi[kt][3] = pack_hi(x11.x, x11.y, ra, rb); Alo[kt][3] = pack_bf(ra, rb);
        }

        layer_mma<3, 16>(Ahi, Alo, smw + OFF_L1, S1, grp, tig, D);
        epi128(D, Pb, 0, tig, Ahi, Alo);
        layer_mma<8, 16>(Ahi, Alo, smw + OFF_L2, S2, grp, tig, D);
        epi128(D, Pb, 384, tig, Ahi, Alo);
        layer_mma<8, 16>(Ahi, Alo, smw + OFF_L3, S2, grp, tig, D);
        epi128(D, Pb, 768, tig, Ahi, Alo);
        layer_mma<8, 2>(Ahi, Alo, smw + OFF_L4, S2, grp, tig, D);

        // ---- layer-4 epilogue: LN(16)+tanh, write out ----
        {
            float2 bb0 = *(const float2*)&Pb[1152 + tig * 2];
            float2 bb1 = *(const float2*)&Pb[1152 + 8 + tig * 2];
            float v00 = D[0][0] + bb0.x, v01 = D[0][1] + bb0.y;
            float v02 = D[1][0] + bb1.x, v03 = D[1][1] + bb1.y;
            float v10 = D[0][2] + bb0.x, v11 = D[0][3] + bb0.y;
            float v12 = D[1][2] + bb1.x, v13 = D[1][3] + bb1.y;
            float s0 = (v00 + v01) + (v02 + v03);
            float q0 = fmaf(v00, v00, fmaf(v01, v01, fmaf(v02, v02, v03 * v03)));
            float s1 = (v10 + v11) + (v12 + v13);
            float q1 = fmaf(v10, v10, fmaf(v11, v11, fmaf(v12, v12, v13 * v13)));
            s0 += __shfl_xor_sync(0xffffffffu, s0, 1); q0 += __shfl_xor_sync(0xffffffffu, q0, 1);
            s0 += __shfl_xor_sync(0xffffffffu, s0, 2); q0 += __shfl_xor_sync(0xffffffffu, q0, 2);
            s1 += __shfl_xor_sync(0xffffffffu, s1, 1); q1 += __shfl_xor_sync(0xffffffffu, q1, 1);
            s1 += __shfl_xor_sync(0xffffffffu, s1, 2); q1 += __shfl_xor_sync(0xffffffffu, q1, 2);
            float m0 = s0 * (1.0f / 16.0f);
            float w0 = fmaxf(q0 * (1.0f / 16.0f) - m0 * m0, 0.0f);
            float rs0 = rsqrtf(w0 + LN_EPS);
            float m1 = s1 * (1.0f / 16.0f);
            float w1 = fmaxf(q1 * (1.0f / 16.0f) - m1 * m1, 0.0f);
            float rs1 = rsqrtf(w1 + LN_EPS);
            float2 gg0 = *(const float2*)&Pb[1168 + tig * 2];
            float2 gg1 = *(const float2*)&Pb[1168 + 8 + tig * 2];
            float2 be0 = *(const float2*)&Pb[1184 + tig * 2];
            float2 be1v = *(const float2*)&Pb[1184 + 8 + tig * 2];
            float2 o;
            o.x = ftanh(fmaf((v00 - m0) * rs0, gg0.x, be0.x));
            o.y = ftanh(fmaf((v01 - m0) * rs0, gg0.y, be0.y));
            *(float2*)&out[r0 * 16 + tig * 2] = o;
            o.x = ftanh(fmaf((v02 - m0) * rs0, gg1.x, be1v.x));
            o.y = ftanh(fmaf((v03 - m0) * rs0, gg1.y, be1v.y));
            *(float2*)&out[r0 * 16 + 8 + tig * 2] = o;
            o.x = ftanh(fmaf((v10 - m1) * rs1, gg0.x, be0.x));
            o.y = ftanh(fmaf((v11 - m1) * rs1, gg0.y, be0.y));
            *(float2*)&out[r1 * 16 + tig * 2] = o;
            o.x = ftanh(fmaf((v12 - m1) * rs1, gg1.x, be1v.x));
            o.y = ftanh(fmaf((v13 - m1) * rs1, gg1.y, be1v.y));
            *(float2*)&out[r1 * 16 + 8 + tig * 2] = o;
        }
    }
}

// ---------------- launch -----------------------------------------------------
extern "C" void kernel_launch(void* const* d_in, const int* in_sizes, int n_in,
                              void* d_out, int out_size) {
    const float* nodes = (const float*)d_in[0];
    const int2*  edges = (const int2*) d_in[1];
    const float* ew    = (const float*)d_in[2];
    const float* W1 = (const float*)d_in[3];
    const float* b1 = (const float*)d_in[4];
    const float* g1 = (const float*)d_in[5];
    const float* be1= (const float*)d_in[6];
    const float* W2 = (const float*)d_in[7];
    const float* b2 = (const float*)d_in[8];
    const float* g2 = (const float*)d_in[9];
    const float* be2= (const float*)d_in[10];
    const float* W3 = (const float*)d_in[11];
    const float* b3 = (const float*)d_in[12];
    const float* g3 = (const float*)d_in[13];
    const float* be3= (const float*)d_in[14];
    const float* W4 = (const float*)d_in[15];
    const float* b4 = (const float*)d_in[16];
    const float* g4 = (const float*)d_in[17];
    const float* be4= (const float*)d_in[18];
    float* out = (float*)d_out;

    // zero agg buffers via memset nodes (graph-capturable, no kernel launch)
    void* p_in = nullptr; void* p_out = nullptr;
    cudaGetSymbolAddress(&p_in,  g_agg_in);
    cudaGetSymbolAddress(&p_out, g_agg_out);
    cudaMemsetAsync(p_in,  0, N_NODES * 16 * sizeof(float));
    cudaMemsetAsync(p_out, 0, N_NODES * 16 * sizeof(float));

    scatter_kernel<<<(E_EDGES * 4 + 255) / 256, 256>>>(nodes, edges, ew);

    int smCount = 148;
    cudaDeviceGetAttribute(&smCount, cudaDevAttrMultiProcessorCount, 0);
    cudaFuncSetAttribute(mlp_kernel, cudaFuncAttributeMaxDynamicSharedMemorySize, SMEM_BYTES);
    mlp_kernel<<<smCount, 256, SMEM_BYTES>>>(nodes,
                                             W1, b1, g1, be1,
                                             W2, b2, g2, be2,
                                             W3, b3, g3, be3,
                                             W4, b4, g4, be4,
                                             out);
}